// round 1
// baseline (speedup 1.0000x reference)
#include <cuda_runtime.h>
#include <cstdint>

#define M_NODES 100000
#define IN_DIM  128
#define OUT_DIM 64

// Scratch for h = x @ W  (25.6 MB). Device-global array: allocation-free.
__device__ float g_h[(size_t)M_NODES * OUT_DIM];

// ---------------------------------------------------------------------------
// Kernel 1: out[i*64 + c] = bias[c]   (d_out is poisoned, must init)
// ---------------------------------------------------------------------------
__global__ void init_out_kernel(float* __restrict__ out,
                                const float* __restrict__ bias, int total) {
    int i = blockIdx.x * blockDim.x + threadIdx.x;
    if (i < total) out[i] = bias[i & (OUT_DIM - 1)];
}

// ---------------------------------------------------------------------------
// Kernel 2: h = x @ W.  Register-tiled SGEMM.
// BM=128 rows, BN=64 (full out-dim), BK=16.  128 threads, each 8x8 tile.
// ---------------------------------------------------------------------------
__global__ __launch_bounds__(128)
void gemm_kernel(const float* __restrict__ x, const float* __restrict__ W, int M) {
    __shared__ float xs[16][128];      // [k][row]
    __shared__ float ws[16][64];       // [k][col]

    const int tid = threadIdx.x;            // 0..127
    const int tx  = tid & 7;                // col-tile 0..7  (cols tx*8..tx*8+7)
    const int ty  = tid >> 3;               // row-tile 0..15 (rows ty*8..ty*8+7)
    const int block_row = blockIdx.x * 128;

    float acc[8][8];
#pragma unroll
    for (int i = 0; i < 8; i++)
#pragma unroll
        for (int j = 0; j < 8; j++) acc[i][j] = 0.f;

    for (int k0 = 0; k0 < IN_DIM; k0 += 16) {
        // --- load x tile: thread t loads row t's 16 k-values (4x LDG.128),
        //     stores transposed (conflict-free: all lanes same k, consecutive rows)
        {
            const int grow = block_row + tid;
            float4 v0, v1, v2, v3;
            if (grow < M) {
                const float4* p = reinterpret_cast<const float4*>(
                    x + (size_t)grow * IN_DIM + k0);
                v0 = p[0]; v1 = p[1]; v2 = p[2]; v3 = p[3];
            } else {
                v0 = v1 = v2 = v3 = make_float4(0.f, 0.f, 0.f, 0.f);
            }
            xs[0][tid]  = v0.x; xs[1][tid]  = v0.y; xs[2][tid]  = v0.z; xs[3][tid]  = v0.w;
            xs[4][tid]  = v1.x; xs[5][tid]  = v1.y; xs[6][tid]  = v1.z; xs[7][tid]  = v1.w;
            xs[8][tid]  = v2.x; xs[9][tid]  = v2.y; xs[10][tid] = v2.z; xs[11][tid] = v2.w;
            xs[12][tid] = v3.x; xs[13][tid] = v3.y; xs[14][tid] = v3.z; xs[15][tid] = v3.w;
        }
        // --- load W tile: 16x64 = 1024 floats, 2x float4 per thread, coalesced
        {
            const int flat = tid * 8;            // 0..1016
            const int kk = flat >> 6;            // /64
            const int cc = flat & 63;
            const float4* p = reinterpret_cast<const float4*>(
                W + (size_t)(k0 + kk) * OUT_DIM + cc);
            float4 a = p[0], b = p[1];
            *reinterpret_cast<float4*>(&ws[kk][cc])     = a;
            *reinterpret_cast<float4*>(&ws[kk][cc + 4]) = b;
        }
        __syncthreads();

#pragma unroll
        for (int kk = 0; kk < 16; kk++) {
            float4 a0 = *reinterpret_cast<const float4*>(&xs[kk][ty * 8]);
            float4 a1 = *reinterpret_cast<const float4*>(&xs[kk][ty * 8 + 4]);
            float4 b0 = *reinterpret_cast<const float4*>(&ws[kk][tx * 8]);
            float4 b1 = *reinterpret_cast<const float4*>(&ws[kk][tx * 8 + 4]);
            float ar[8] = {a0.x, a0.y, a0.z, a0.w, a1.x, a1.y, a1.z, a1.w};
            float br[8] = {b0.x, b0.y, b0.z, b0.w, b1.x, b1.y, b1.z, b1.w};
#pragma unroll
            for (int i = 0; i < 8; i++)
#pragma unroll
                for (int j = 0; j < 8; j++)
                    acc[i][j] = fmaf(ar[i], br[j], acc[i][j]);
        }
        __syncthreads();
    }

    // epilogue: rows block_row + ty*8 + i, cols tx*8 .. tx*8+7
#pragma unroll
    for (int i = 0; i < 8; i++) {
        const int grow = block_row + ty * 8 + i;
        if (grow < M) {
            float* p = g_h + (size_t)grow * OUT_DIM + tx * 8;
            *reinterpret_cast<float4*>(p)     = make_float4(acc[i][0], acc[i][1], acc[i][2], acc[i][3]);
            *reinterpret_cast<float4*>(p + 4) = make_float4(acc[i][4], acc[i][5], acc[i][6], acc[i][7]);
        }
    }
}

// ---------------------------------------------------------------------------
// Kernel 3: scatter  out[dst] += w_e * h[src]
// One thread per (edge, 4-col chunk): 16 threads/edge.
// Vectorized L2 reduction: red.global.add.v4.f32 (sm_90+).
// ---------------------------------------------------------------------------
__global__ __launch_bounds__(256)
void scatter_kernel(const int* __restrict__ ei, const float* __restrict__ ew,
                    float* __restrict__ out, int E) {
    const int idx = blockIdx.x * blockDim.x + threadIdx.x;
    const int e = idx >> 4;
    if (e >= E) return;
    const int c = (idx & 15) << 2;

    const int   dst = __ldg(ei + e);         // edge_index[0][e]
    const int   src = __ldg(ei + E + e);     // edge_index[1][e]
    const float w   = __ldg(ew + e);

    const float4 v = *reinterpret_cast<const float4*>(
        g_h + (size_t)src * OUT_DIM + c);

    float* p = out + (size_t)dst * OUT_DIM + c;
    asm volatile("red.global.add.v4.f32 [%0], {%1, %2, %3, %4};"
                 :: "l"(p), "f"(v.x * w), "f"(v.y * w), "f"(v.z * w), "f"(v.w * w)
                 : "memory");
}

// ---------------------------------------------------------------------------
// Launch
// ---------------------------------------------------------------------------
extern "C" void kernel_launch(void* const* d_in, const int* in_sizes, int n_in,
                              void* d_out, int out_size) {
    const float* x    = (const float*)d_in[0];   // [N, 128]
    const int*   ei   = (const int*)  d_in[1];   // [2, E]
    const float* ew   = (const float*)d_in[2];   // [E]
    const float* W    = (const float*)d_in[3];   // [128, 64]
    const float* bias = (const float*)d_in[4];   // [64]
    float* out = (float*)d_out;                  // [N, 64]

    const int M = in_sizes[0] / IN_DIM;          // 100000
    const int E = in_sizes[2];                   // 1600000

    // 1) out = bias (broadcast)
    {
        const int total = M * OUT_DIM;
        init_out_kernel<<<(total + 255) / 256, 256>>>(out, bias, total);
    }
    // 2) h = x @ W
    {
        const int grid = (M + 127) / 128;
        gemm_kernel<<<grid, 128>>>(x, W, M);
    }
    // 3) out[dst] += w_e * h[src]
    {
        const long long total = (long long)E * 16;
        const int grid = (int)((total + 255) / 256);
        scatter_kernel<<<grid, 256>>>(ei, ew, out, E);
    }
}

// round 2
// speedup vs baseline: 1.1473x; 1.1473x over previous
#include <cuda_runtime.h>
#include <cstdint>

#define M_NODES 100000
#define IN_DIM  128
#define OUT_DIM 64
#define E_MAX   1600000

#define NBLK_SCAN ((M_NODES + 255) / 256)          // 391
#define N_PAD     (NBLK_SCAN * 256)                // 100096

// ---- Device scratch (allocation-free) ----
__device__ float g_h[(size_t)M_NODES * OUT_DIM];   // h = x @ W    (25.6 MB)
__device__ int   g_count[N_PAD];                   // per-dst degree
__device__ int   g_off[N_PAD + 1];                 // exclusive offsets (CSR)
__device__ int   g_pos[N_PAD];                     // running fill positions
__device__ int   g_bsum[512];                      // block sums for scan
__device__ int   g_src_sorted[E_MAX];              // CSR src indices
__device__ float g_w_sorted[E_MAX];                // CSR edge weights

// ---------------------------------------------------------------------------
// K1: zero the degree counters (incl. padding)
// ---------------------------------------------------------------------------
__global__ void zero_counts_kernel() {
    int i = blockIdx.x * blockDim.x + threadIdx.x;
    if (i < N_PAD) g_count[i] = 0;
}

// ---------------------------------------------------------------------------
// K2: h = x @ W.  Register-tiled SGEMM (BM=128, BN=64, BK=16; 8x8/thread)
// ---------------------------------------------------------------------------
__global__ __launch_bounds__(128)
void gemm_kernel(const float* __restrict__ x, const float* __restrict__ W, int M) {
    __shared__ float xs[16][128];
    __shared__ float ws[16][64];

    const int tid = threadIdx.x;
    const int tx  = tid & 7;
    const int ty  = tid >> 3;
    const int block_row = blockIdx.x * 128;

    float acc[8][8];
#pragma unroll
    for (int i = 0; i < 8; i++)
#pragma unroll
        for (int j = 0; j < 8; j++) acc[i][j] = 0.f;

    for (int k0 = 0; k0 < IN_DIM; k0 += 16) {
        {
            const int grow = block_row + tid;
            float4 v0, v1, v2, v3;
            if (grow < M) {
                const float4* p = reinterpret_cast<const float4*>(
                    x + (size_t)grow * IN_DIM + k0);
                v0 = p[0]; v1 = p[1]; v2 = p[2]; v3 = p[3];
            } else {
                v0 = v1 = v2 = v3 = make_float4(0.f, 0.f, 0.f, 0.f);
            }
            xs[0][tid]  = v0.x; xs[1][tid]  = v0.y; xs[2][tid]  = v0.z; xs[3][tid]  = v0.w;
            xs[4][tid]  = v1.x; xs[5][tid]  = v1.y; xs[6][tid]  = v1.z; xs[7][tid]  = v1.w;
            xs[8][tid]  = v2.x; xs[9][tid]  = v2.y; xs[10][tid] = v2.z; xs[11][tid] = v2.w;
            xs[12][tid] = v3.x; xs[13][tid] = v3.y; xs[14][tid] = v3.z; xs[15][tid] = v3.w;
        }
        {
            const int flat = tid * 8;
            const int kk = flat >> 6;
            const int cc = flat & 63;
            const float4* p = reinterpret_cast<const float4*>(
                W + (size_t)(k0 + kk) * OUT_DIM + cc);
            float4 a = p[0], b = p[1];
            *reinterpret_cast<float4*>(&ws[kk][cc])     = a;
            *reinterpret_cast<float4*>(&ws[kk][cc + 4]) = b;
        }
        __syncthreads();

#pragma unroll
        for (int kk = 0; kk < 16; kk++) {
            float4 a0 = *reinterpret_cast<const float4*>(&xs[kk][ty * 8]);
            float4 a1 = *reinterpret_cast<const float4*>(&xs[kk][ty * 8 + 4]);
            float4 b0 = *reinterpret_cast<const float4*>(&ws[kk][tx * 8]);
            float4 b1 = *reinterpret_cast<const float4*>(&ws[kk][tx * 8 + 4]);
            float ar[8] = {a0.x, a0.y, a0.z, a0.w, a1.x, a1.y, a1.z, a1.w};
            float br[8] = {b0.x, b0.y, b0.z, b0.w, b1.x, b1.y, b1.z, b1.w};
#pragma unroll
            for (int i = 0; i < 8; i++)
#pragma unroll
                for (int j = 0; j < 8; j++)
                    acc[i][j] = fmaf(ar[i], br[j], acc[i][j]);
        }
        __syncthreads();
    }

#pragma unroll
    for (int i = 0; i < 8; i++) {
        const int grow = block_row + ty * 8 + i;
        if (grow < M) {
            float* p = g_h + (size_t)grow * OUT_DIM + tx * 8;
            *reinterpret_cast<float4*>(p)     = make_float4(acc[i][0], acc[i][1], acc[i][2], acc[i][3]);
            *reinterpret_cast<float4*>(p + 4) = make_float4(acc[i][4], acc[i][5], acc[i][6], acc[i][7]);
        }
    }
}

// ---------------------------------------------------------------------------
// K3: histogram of dst degrees
// ---------------------------------------------------------------------------
__global__ __launch_bounds__(256)
void hist_kernel(const int* __restrict__ ei, int E) {
    int e = blockIdx.x * blockDim.x + threadIdx.x;
    if (e < E) atomicAdd(&g_count[ei[e]], 1);
}

// ---------------------------------------------------------------------------
// K4/K5/K6: 3-phase exclusive scan over g_count -> g_off
// ---------------------------------------------------------------------------
__global__ __launch_bounds__(256)
void scan1_kernel() {
    __shared__ int s[256];
    const int tid = threadIdx.x;
    const int i = blockIdx.x * 256 + tid;
    int v = g_count[i];
    s[tid] = v;
    __syncthreads();
#pragma unroll
    for (int d = 1; d < 256; d <<= 1) {
        int t = (tid >= d) ? s[tid - d] : 0;
        __syncthreads();
        s[tid] += t;
        __syncthreads();
    }
    g_off[i] = s[tid] - v;                // exclusive within block
    if (tid == 255) g_bsum[blockIdx.x] = s[255];
}

__global__ __launch_bounds__(512)
void scan2_kernel() {
    __shared__ int s[512];
    const int tid = threadIdx.x;
    int v = (tid < NBLK_SCAN) ? g_bsum[tid] : 0;
    s[tid] = v;
    __syncthreads();
#pragma unroll
    for (int d = 1; d < 512; d <<= 1) {
        int t = (tid >= d) ? s[tid - d] : 0;
        __syncthreads();
        s[tid] += t;
        __syncthreads();
    }
    g_bsum[tid] = s[tid] - v;             // exclusive block offsets
}

__global__ __launch_bounds__(256)
void scan3_kernel() {
    const int i = blockIdx.x * 256 + threadIdx.x;
    int o = g_off[i] + g_bsum[blockIdx.x];
    g_off[i] = o;
    g_pos[i] = o;
    if (i == 0) g_off[N_PAD] = g_off[N_PAD - 1];  // harmless tail (padding is zero-count)
}

// ---------------------------------------------------------------------------
// K7: bin edges into CSR order
// ---------------------------------------------------------------------------
__global__ __launch_bounds__(256)
void bin_kernel(const int* __restrict__ ei, const float* __restrict__ ew, int E) {
    int e = blockIdx.x * blockDim.x + threadIdx.x;
    if (e >= E) return;
    const int dst = ei[e];
    const int src = ei[E + e];
    const float w = ew[e];
    int p = atomicAdd(&g_pos[dst], 1);
    g_src_sorted[p] = src;
    g_w_sorted[p]   = w;
}

// ---------------------------------------------------------------------------
// K8: aggregation — one warp per node, coalesced gather, no atomics
// ---------------------------------------------------------------------------
__global__ __launch_bounds__(256)
void aggregate_kernel(const float* __restrict__ bias, float* __restrict__ out, int N) {
    const int warp = (blockIdx.x * blockDim.x + threadIdx.x) >> 5;
    const int lane = threadIdx.x & 31;
    if (warp >= N) return;

    const int beg = g_off[warp];
    const int end = g_off[warp + 1];

    float2 acc = make_float2(0.f, 0.f);

    for (int base = beg; base < end; base += 32) {
        const int n = min(32, end - base);
        int   sv = 0;
        float wv = 0.f;
        if (lane < n) {
            sv = g_src_sorted[base + lane];
            wv = g_w_sorted[base + lane];
        }
#pragma unroll 4
        for (int j = 0; j < n; j++) {
            const int   s = __shfl_sync(0xffffffffu, sv, j);
            const float w = __shfl_sync(0xffffffffu, wv, j);
            const float2 v = *reinterpret_cast<const float2*>(
                g_h + (size_t)s * OUT_DIM + lane * 2);
            acc.x = fmaf(w, v.x, acc.x);
            acc.y = fmaf(w, v.y, acc.y);
        }
    }

    const float2 b = reinterpret_cast<const float2*>(bias)[lane];
    acc.x += b.x;
    acc.y += b.y;
    *reinterpret_cast<float2*>(out + (size_t)warp * OUT_DIM + lane * 2) = acc;
}

// ---------------------------------------------------------------------------
// Launch
// ---------------------------------------------------------------------------
extern "C" void kernel_launch(void* const* d_in, const int* in_sizes, int n_in,
                              void* d_out, int out_size) {
    const float* x    = (const float*)d_in[0];   // [N, 128]
    const int*   ei   = (const int*)  d_in[1];   // [2, E]
    const float* ew   = (const float*)d_in[2];   // [E]
    const float* W    = (const float*)d_in[3];   // [128, 64]
    const float* bias = (const float*)d_in[4];   // [64]
    float* out = (float*)d_out;                  // [N, 64]

    const int M = in_sizes[0] / IN_DIM;          // 100000
    const int E = in_sizes[2];                   // 1600000

    zero_counts_kernel<<<(N_PAD + 255) / 256, 256>>>();
    gemm_kernel<<<(M + 127) / 128, 128>>>(x, W, M);
    hist_kernel<<<(E + 255) / 256, 256>>>(ei, E);
    scan1_kernel<<<NBLK_SCAN, 256>>>();
    scan2_kernel<<<1, 512>>>();
    scan3_kernel<<<NBLK_SCAN, 256>>>();
    bin_kernel<<<(E + 255) / 256, 256>>>(ei, ew, E);
    aggregate_kernel<<<(M * 32 + 255) / 256, 256>>>(bias, out, M);
}

// round 3
// speedup vs baseline: 1.3744x; 1.1979x over previous
#include <cuda_runtime.h>
#include <cstdint>

#define M_NODES 100000
#define IN_DIM  128
#define OUT_DIM 64
#define E_MAX   1600000

#define NBLK_SCAN ((M_NODES + 255) / 256)          // 391
#define N_PAD     (NBLK_SCAN * 256)                // 100096

// ---- Device scratch (allocation-free) ----
__device__ float g_h[(size_t)M_NODES * OUT_DIM];   // h = x @ W (25.6 MB)
__device__ int   g_count[N_PAD];
__device__ int   g_off[N_PAD + 1];
__device__ int   g_pos[N_PAD];
__device__ int   g_bsum[512];
__device__ int2  g_es[E_MAX];                      // CSR (src, w-bits) interleaved

// ---------------------------------------------------------------------------
__global__ void zero_counts_kernel() {
    int i = blockIdx.x * blockDim.x + threadIdx.x;
    if (i < N_PAD) g_count[i] = 0;
}

// ---------------------------------------------------------------------------
// GEMM: h = x @ W via tensor cores (mma.sync m16n8k8 tf32, 3-pass split).
// Block: 256 thr (8 warps). Tile: 128 rows x 64 cols, K=128.
// xs[128][36] (pad 36: A-frag LDS conflict-free), ws[64][132] transposed
// (pad 132: B-frag bank = (4*gid + tg + c) % 32, conflict-free).
// ---------------------------------------------------------------------------
__device__ __forceinline__ float cvt_tf32(float a) {
    float r;
    asm("cvt.rna.tf32.f32 %0, %1;" : "=f"(r) : "f"(a));
    return r;
}
__device__ __forceinline__ void mma_tf32(float* d, const float* a, const float* b) {
    asm volatile(
        "mma.sync.aligned.m16n8k8.row.col.f32.tf32.tf32.f32 "
        "{%0,%1,%2,%3}, {%4,%5,%6,%7}, {%8,%9}, {%0,%1,%2,%3};"
        : "+f"(d[0]), "+f"(d[1]), "+f"(d[2]), "+f"(d[3])
        : "f"(a[0]), "f"(a[1]), "f"(a[2]), "f"(a[3]), "f"(b[0]), "f"(b[1]));
}

__global__ __launch_bounds__(256)
void gemm_kernel(const float* __restrict__ x, const float* __restrict__ W, int M) {
    __shared__ float xs[128][36];     // 18.4 KB, chunk of 32 k-values
    __shared__ float ws[64][132];     // 33.8 KB, W transposed [n][k], full K

    const int tid  = threadIdx.x;
    const int warp = tid >> 5;
    const int lane = tid & 31;
    const int gid  = lane >> 2;       // 0..7
    const int tg   = lane & 3;        // 0..3
    const int block_row = blockIdx.x * 128;
    const int wrow = warp * 16;       // warp's row offset in tile

    // --- Load full W transposed into smem: ws[n][k] = W[k*64 + n]
    //     8192 elems / 256 thr = 32 each; coalesced global reads.
    for (int i = tid; i < IN_DIM * OUT_DIM; i += 256) {
        const int k = i >> 6;         // i / 64
        const int n = i & 63;
        ws[n][k] = W[i];
    }

    float acc[8][4];
#pragma unroll
    for (int t = 0; t < 8; t++)
#pragma unroll
        for (int j = 0; j < 4; j++) acc[t][j] = 0.f;

    for (int c = 0; c < 4; c++) {                 // K chunks of 32
        const int k0 = c * 32;
        // load x chunk: 128 rows x 32 k = 1024 float4, 4 per thread
        __syncthreads();
#pragma unroll
        for (int t = 0; t < 4; t++) {
            const int i   = tid + t * 256;        // 0..1023
            const int row = i >> 3;
            const int c4  = i & 7;
            const int grow = block_row + row;
            float4 v = make_float4(0.f, 0.f, 0.f, 0.f);
            if (grow < M)
                v = *reinterpret_cast<const float4*>(
                    x + (size_t)grow * IN_DIM + k0 + c4 * 4);
            *reinterpret_cast<float4*>(&xs[row][c4 * 4]) = v;
        }
        __syncthreads();

#pragma unroll
        for (int s = 0; s < 4; s++) {             // k8 steps within chunk
            const int kk = s * 8;
            // A fragment (raw fp32) + split
            float ar[4], ah[4], al[4];
            ar[0] = xs[wrow + gid][kk + tg];
            ar[1] = xs[wrow + gid + 8][kk + tg];
            ar[2] = xs[wrow + gid][kk + tg + 4];
            ar[3] = xs[wrow + gid + 8][kk + tg + 4];
#pragma unroll
            for (int j = 0; j < 4; j++) {
                ah[j] = cvt_tf32(ar[j]);
                al[j] = ar[j] - ah[j];             // fed raw (HW truncates to tf32)
            }
#pragma unroll
            for (int t = 0; t < 8; t++) {          // 8 n-tiles of 8 cols
                const int n0 = t * 8;
                float br[2], bh[2], bl[2];
                br[0] = ws[n0 + gid][k0 + kk + tg];
                br[1] = ws[n0 + gid][k0 + kk + tg + 4];
                bh[0] = cvt_tf32(br[0]); bl[0] = br[0] - bh[0];
                bh[1] = cvt_tf32(br[1]); bl[1] = br[1] - bh[1];
                mma_tf32(acc[t], ah, bh);
                mma_tf32(acc[t], al, bh);
                mma_tf32(acc[t], ah, bl);
            }
        }
    }

    // Epilogue: c0,c1 -> (r0, 2tg..2tg+1); c2,c3 -> (r0+8, ...)
    const int r0 = block_row + wrow + gid;
    const int r1 = r0 + 8;
#pragma unroll
    for (int t = 0; t < 8; t++) {
        const int col = t * 8 + tg * 2;
        if (r0 < M)
            *reinterpret_cast<float2*>(g_h + (size_t)r0 * OUT_DIM + col) =
                make_float2(acc[t][0], acc[t][1]);
        if (r1 < M)
            *reinterpret_cast<float2*>(g_h + (size_t)r1 * OUT_DIM + col) =
                make_float2(acc[t][2], acc[t][3]);
    }
}

// ---------------------------------------------------------------------------
__global__ __launch_bounds__(256)
void hist_kernel(const int* __restrict__ ei, int E) {
    int e = blockIdx.x * blockDim.x + threadIdx.x;
    if (e < E) atomicAdd(&g_count[ei[e]], 1);
}

// ---------------------------------------------------------------------------
// Shuffle-based scans
// ---------------------------------------------------------------------------
__device__ __forceinline__ int warp_incl_scan(int v, int lane) {
#pragma unroll
    for (int d = 1; d < 32; d <<= 1) {
        int t = __shfl_up_sync(0xffffffffu, v, d);
        if (lane >= d) v += t;
    }
    return v;
}

__global__ __launch_bounds__(256)
void scan1_kernel() {
    __shared__ int wsum[8];
    const int tid  = threadIdx.x;
    const int lane = tid & 31;
    const int wid  = tid >> 5;
    const int i = blockIdx.x * 256 + tid;
    const int v = g_count[i];
    int s = warp_incl_scan(v, lane);
    if (lane == 31) wsum[wid] = s;
    __syncthreads();
    if (wid == 0) {
        int ws_ = (lane < 8) ? wsum[lane] : 0;
        ws_ = warp_incl_scan(ws_, lane);
        if (lane < 8) wsum[lane] = ws_;
    }
    __syncthreads();
    const int base = (wid > 0) ? wsum[wid - 1] : 0;
    g_off[i] = base + s - v;
    if (tid == 255) g_bsum[blockIdx.x] = base + s;
}

__global__ __launch_bounds__(512)
void scan2_kernel() {
    __shared__ int wsum[16];
    const int tid  = threadIdx.x;
    const int lane = tid & 31;
    const int wid  = tid >> 5;
    const int v = (tid < NBLK_SCAN) ? g_bsum[tid] : 0;
    int s = warp_incl_scan(v, lane);
    if (lane == 31) wsum[wid] = s;
    __syncthreads();
    if (wid == 0) {
        int ws_ = (lane < 16) ? wsum[lane] : 0;
        ws_ = warp_incl_scan(ws_, lane);
        if (lane < 16) wsum[lane] = ws_;
    }
    __syncthreads();
    const int base = (wid > 0) ? wsum[wid - 1] : 0;
    g_bsum[tid] = base + s - v;
}

__global__ __launch_bounds__(256)
void scan3_kernel() {
    const int i = blockIdx.x * 256 + threadIdx.x;
    int o = g_off[i] + g_bsum[blockIdx.x];
    g_off[i] = o;
    g_pos[i] = o;
    if (i == 0) g_off[N_PAD] = g_off[N_PAD - 1];
}

// ---------------------------------------------------------------------------
__global__ __launch_bounds__(256)
void bin_kernel(const int* __restrict__ ei, const float* __restrict__ ew, int E) {
    int e = blockIdx.x * blockDim.x + threadIdx.x;
    if (e >= E) return;
    const int dst = ei[e];
    const int src = ei[E + e];
    const float w = ew[e];
    int p = atomicAdd(&g_pos[dst], 1);
    g_es[p] = make_int2(src, __float_as_int(w));
}

// ---------------------------------------------------------------------------
// Aggregation: one warp per node, coalesced gather, no atomics.
// ---------------------------------------------------------------------------
__global__ __launch_bounds__(256)
void aggregate_kernel(const float* __restrict__ bias, float* __restrict__ out, int N) {
    const int warp = (blockIdx.x * blockDim.x + threadIdx.x) >> 5;
    const int lane = threadIdx.x & 31;
    if (warp >= N) return;

    const int beg = g_off[warp];
    const int end = g_off[warp + 1];

    float2 acc = make_float2(0.f, 0.f);

    for (int base = beg; base < end; base += 32) {
        const int n = min(32, end - base);
        int   sv = 0;
        float wv = 0.f;
        if (lane < n) {
            const int2 e = __ldg(&g_es[base + lane]);
            sv = e.x;
            wv = __int_as_float(e.y);
        }
#pragma unroll 4
        for (int j = 0; j < n; j++) {
            const int   s = __shfl_sync(0xffffffffu, sv, j);
            const float w = __shfl_sync(0xffffffffu, wv, j);
            const float2 v = *reinterpret_cast<const float2*>(
                g_h + (size_t)s * OUT_DIM + lane * 2);
            acc.x = fmaf(w, v.x, acc.x);
            acc.y = fmaf(w, v.y, acc.y);
        }
    }

    const float2 b = reinterpret_cast<const float2*>(bias)[lane];
    acc.x += b.x;
    acc.y += b.y;
    *reinterpret_cast<float2*>(out + (size_t)warp * OUT_DIM + lane * 2) = acc;
}

// ---------------------------------------------------------------------------
extern "C" void kernel_launch(void* const* d_in, const int* in_sizes, int n_in,
                              void* d_out, int out_size) {
    const float* x    = (const float*)d_in[0];   // [N, 128]
    const int*   ei   = (const int*)  d_in[1];   // [2, E]
    const float* ew   = (const float*)d_in[2];   // [E]
    const float* W    = (const float*)d_in[3];   // [128, 64]
    const float* bias = (const float*)d_in[4];   // [64]
    float* out = (float*)d_out;                  // [N, 64]

    const int M = in_sizes[0] / IN_DIM;          // 100000
    const int E = in_sizes[2];                   // 1600000

    zero_counts_kernel<<<(N_PAD + 255) / 256, 256>>>();
    gemm_kernel<<<(M + 127) / 128, 256>>>(x, W, M);
    hist_kernel<<<(E + 255) / 256, 256>>>(ei, E);
    scan1_kernel<<<NBLK_SCAN, 256>>>();
    scan2_kernel<<<1, 512>>>();
    scan3_kernel<<<NBLK_SCAN, 256>>>();
    bin_kernel<<<(E + 255) / 256, 256>>>(ei, ew, E);
    aggregate_kernel<<<(M * 32 + 255) / 256, 256>>>(bias, out, M);
}